// round 1
// baseline (speedup 1.0000x reference)
#include <cuda_runtime.h>
#include <stdint.h>

// SpikeFP8Adder_Spatial: soft-logic E4M3 adder on {0,1}-valued float bit vectors.
// Inputs are exact 0.0/1.0 floats, so the gate network is emulated exactly with
// integer bit logic. Memory-bound: 384 MB total traffic.

__global__ __launch_bounds__(256) void fp8add_kernel(
    const uint4* __restrict__ A,   // 2*N elements of uint4 (each row = 2 x uint4)
    const uint4* __restrict__ B,
    uint4* __restrict__ O,
    int nrows)
{
    int i = blockIdx.x * blockDim.x + threadIdx.x;
    if (i >= nrows) return;

    // Load 8 floats (as raw uints) per operand: two 16B vectors each.
    uint4 a0 = A[2 * i + 0];
    uint4 a1 = A[2 * i + 1];
    uint4 b0 = B[2 * i + 0];
    uint4 b1 = B[2 * i + 1];

    // Pack MSB-first: index 0 -> bit7 ... index 7 -> bit0. Value is 1 iff raw != 0.
    unsigned pa =
        ((a0.x != 0u) << 7) | ((a0.y != 0u) << 6) | ((a0.z != 0u) << 5) | ((a0.w != 0u) << 4) |
        ((a1.x != 0u) << 3) | ((a1.y != 0u) << 2) | ((a1.z != 0u) << 1) |  (a1.w != 0u);
    unsigned pb =
        ((b0.x != 0u) << 7) | ((b0.y != 0u) << 6) | ((b0.z != 0u) << 5) | ((b0.w != 0u) << 4) |
        ((b1.x != 0u) << 3) | ((b1.y != 0u) << 2) | ((b1.z != 0u) << 1) |  (b1.w != 0u);

    unsigned sa = (pa >> 7) & 1u, ea = (pa >> 3) & 15u, ma = pa & 7u;
    unsigned sb = (pb >> 7) & 1u, eb = (pb >> 3) & 15u, mb = pb & 7u;

    // Comparator4: sel = (ea > eb) | (ea == eb)
    bool sel = (ea >= eb);
    unsigned el = sel ? ea : eb;
    unsigned es = sel ? eb : ea;
    unsigned ml = sel ? ma : mb;
    unsigned ms = sel ? mb : ma;
    unsigned sl = sel ? sa : sb;
    unsigned ss = sel ? sb : sa;

    // 4-bit exponent difference (el >= es so no wrap).
    unsigned diff = el - es;

    // 12-bit extended mantissas: [0, hidden, man(3), 0 x 7], MSB-first -> bit10 hidden, bits 9..7 man.
    unsigned extl = ((el != 0u) ? 0x400u : 0u) | (ml << 7);
    unsigned exts = (((es != 0u) ? 0x400u : 0u) | (ms << 7)) >> diff;

    // 12-bit add/sub with wrap (matches ripple carry/borrow mod 4096).
    unsigned mant = (sl == ss) ? ((extl + exts) & 0xFFFu)
                               : ((extl - exts) & 0xFFFu);

    unsigned top8 = mant >> 4;

    // LZD8: clz over 8 bits, saturating at 7 for zero input.
    unsigned lzc = top8 ? (unsigned)(__clz((int)top8) - 24) : 7u;

    unsigned norm = (top8 << lzc) & 0xFFu;

    // exp_new = (el - lzc + 1) mod 16  (4-bit subtract then increment4)
    unsigned en = (el - lzc + 1u) & 15u;

    // Output byte MSB-first: sign | exp(4) | norm bits 6..4
    // Materialize floats as integer bit patterns: 1.0f = 0x3F800000.
    const unsigned ONE = 0x3F800000u;
    uint4 o0, o1;
    o0.x = sl * ONE;
    o0.y = ((en >> 3) & 1u) * ONE;
    o0.z = ((en >> 2) & 1u) * ONE;
    o0.w = ((en >> 1) & 1u) * ONE;
    o1.x = (en & 1u) * ONE;
    o1.y = ((norm >> 6) & 1u) * ONE;
    o1.z = ((norm >> 5) & 1u) * ONE;
    o1.w = ((norm >> 4) & 1u) * ONE;

    O[2 * i + 0] = o0;
    O[2 * i + 1] = o1;
}

extern "C" void kernel_launch(void* const* d_in, const int* in_sizes, int n_in,
                              void* d_out, int out_size)
{
    const uint4* A = (const uint4*)d_in[0];
    const uint4* B = (const uint4*)d_in[1];
    uint4* O = (uint4*)d_out;

    int nrows = in_sizes[0] / 8;   // A has N*8 float elements
    int threads = 256;
    int blocks = (nrows + threads - 1) / threads;
    fp8add_kernel<<<blocks, threads>>>(A, B, O, nrows);
}